// round 8
// baseline (speedup 1.0000x reference)
#include <cuda_runtime.h>

#define HW   128
#define IMG  (HW*HW)
#define NB   64

typedef unsigned long long u64;

// Scratch buffers (allocation-free rule: __device__ globals)
__device__ float g_bufA[(size_t)NB * 22 * IMG];  // 22-ch concat buffer; x lives in ch 12..21
__device__ float g_bufB[(size_t)NB * 24 * IMG];
__device__ float g_bufC[(size_t)NB * 24 * IMG];

__device__ __forceinline__ u64 pack2(float v) {
    u64 r; unsigned int x = __float_as_uint(v);
    asm("mov.b64 %0, {%1, %1};" : "=l"(r) : "r"(x));
    return r;
}
__device__ __forceinline__ u64 fma2(u64 a, u64 b, u64 c) {
    u64 d;
    asm("fma.rn.f32x2 %0, %1, %2, %3;" : "=l"(d) : "l"(a), "l"(b), "l"(c));
    return d;
}
__device__ __forceinline__ float2 unpack2(u64 v) {
    unsigned int lo, hi;
    asm("mov.b64 {%0, %1}, %2;" : "=r"(lo), "=r"(hi) : "l"(v));
    return make_float2(__uint_as_float(lo), __uint_as_float(hi));
}

// ---------------------------------------------------------------------------
// Fused per-sample 3x3 conv + eval-BN + ReLU, 6 output channels per CTA.
// 128 threads, tile 64x8, T=4 rows/thread, target 8 CTAs/SM (32 warps).
// acc = 4x3 u64 = 24 regs -> ~60 regs total. Input channels chunked by 6,
// CIN zero-padded to CINP (12/24). Output channels split NHALF ways (2 or 4).
// Weights in smem, groups of 8 floats per (i,k) for aligned LDS.128+LDS.64.
// ---------------------------------------------------------------------------
template<int CIN, int CINP, int NHALF>
__global__ __launch_bounds__(128, 8)
void conv3x3_bn_relu6(const float* __restrict__ in, int in_nch,
                      const float* __restrict__ wflat, int wP, int wbase,
                      const float* __restrict__ gam, const float* __restrict__ bet,
                      const float* __restrict__ mea, const float* __restrict__ varr,
                      int bnoff,
                      float* __restrict__ out, int out_nch)
{
    constexpr int COUT   = 6;
    constexpr int T      = 4;
    constexpr int TILE_X = 64;
    constexpr int TILE_Y = 8;
    constexpr int TXW    = TILE_X + 2;   // 66
    constexpr int TYH    = TILE_Y + 2;   // 10
    constexpr int CHUNK  = 6;
    constexpr int NCH    = CINP / CHUNK; // 2 or 4
    constexpr int NT     = 128;

    extern __shared__ float smem[];
    float* s_in = smem;                          // CHUNK * TYH * TXW floats
    float* s_w  = s_in + CHUNK * TYH * TXW;      // CINP * 9 * 8  ([i][k][o], 8-padded)
    float* s_sc = s_w + CINP * 9 * 8;            // 6
    float* s_bi = s_sc + COUT;                   // 6

    const int tid  = threadIdx.x;
    const int b    = blockIdx.z;
    const int half   = blockIdx.x & (NHALF - 1);
    const int ochoff = half * COUT;
    const int gx0  = (blockIdx.x / NHALF) * TILE_X;
    const int gy0  = blockIdx.y * TILE_Y;

    // --- load + repack weights: [o][i][k] (gmem) -> [i][k][o|pad8] (smem) ---
    const float* wsrc = wflat + (size_t)b * wP + wbase + (size_t)ochoff * CIN * 9;
    for (int idx = tid; idx < CINP * 9 * COUT; idx += NT) {
        int o = idx % COUT;
        int r = idx / COUT;
        int k = r % 9;
        int i = r / 9;
        s_w[(i * 9 + k) * 8 + o] = (i < CIN) ? wsrc[(o * CIN + i) * 9 + k] : 0.f;
    }
    if (tid < COUT) {
        int c = bnoff + ochoff + tid;
        float g = gam[c], bb = bet[c], m = mea[c], v = varr[c];
        float inv = g * rsqrtf(v + 1e-5f);
        s_sc[tid] = inv;
        s_bi[tid] = bb - m * inv;
    }

    const int lane = tid & 31;
    const int warp = tid >> 5;
    const int xl   = (warp & 1) * 32 + lane;   // 0..63
    const int y0   = (warp >> 1) * T;          // 0,4

    u64 acc[T][3];
    #pragma unroll
    for (int p = 0; p < T; p++)
        #pragma unroll
        for (int u = 0; u < 3; u++) acc[p][u] = 0ull;

    const char*  wb8 = (const char*)s_w;
    const float* inb = in + (size_t)b * in_nch * IMG;

    for (int ch = 0; ch < NCH; ch++) {
        __syncthreads();
        // --- stage CHUNK input channels (halo, zero-padded) into smem ---
        #pragma unroll 1
        for (int idx = tid; idx < CHUNK * TYH * TXW; idx += NT) {
            int c = idx % TXW;
            int r = (idx / TXW) % TYH;
            int i = idx / (TXW * TYH);
            int ii = ch * CHUNK + i;
            int gy = gy0 - 1 + r, gx = gx0 - 1 + c;
            float v = 0.f;
            if (ii < CIN && (unsigned)gy < HW && (unsigned)gx < HW)
                v = inb[(size_t)ii * IMG + gy * HW + gx];
            s_in[idx] = v;
        }
        __syncthreads();

        #pragma unroll 2
        for (int i = 0; i < CHUNK; i++) {
            const int ii = ch * CHUNK + i;
            const float* srow = &s_in[(i * TYH + y0) * TXW + xl];
            #pragma unroll
            for (int kx = 0; kx < 3; kx++) {
                u64 vr[T + 2];
                #pragma unroll
                for (int r = 0; r < T + 2; r++)
                    vr[r] = pack2(srow[r * TXW + kx]);
                #pragma unroll
                for (int ky = 0; ky < 3; ky++) {
                    // 6 weights for (ii,ky,kx): LDS.128 + LDS.64 (32B-aligned group)
                    const char* wp = wb8 + (size_t)((ii * 9 + ky * 3 + kx) * 8) * 4;
                    ulonglong2 w01 = *(const ulonglong2*)wp;         // (w0,w1),(w2,w3)
                    u64        w2  = *(const u64*)(wp + 16);         // (w4,w5)
                    #pragma unroll
                    for (int p = 0; p < T; p++) {
                        acc[p][0] = fma2(vr[p + ky], w01.x, acc[p][0]);
                        acc[p][1] = fma2(vr[p + ky], w01.y, acc[p][1]);
                        acc[p][2] = fma2(vr[p + ky], w2,    acc[p][2]);
                    }
                }
            }
        }
    }

    // --- epilogue: BN (eval) + ReLU + store ---
    float* ob = out + (size_t)b * out_nch * IMG + (size_t)ochoff * IMG;
    #pragma unroll
    for (int p = 0; p < T; p++) {
        const int y = gy0 + y0 + p;
        const int x = gx0 + xl;
        float* op = ob + y * HW + x;
        #pragma unroll
        for (int u = 0; u < 3; u++) {
            float2 a = unpack2(acc[p][u]);
            int o0 = 2 * u, o1 = 2 * u + 1;
            float r0 = fmaf(a.x, s_sc[o0], s_bi[o0]);
            float r1 = fmaf(a.y, s_sc[o1], s_bi[o1]);
            op[(size_t)o0 * IMG] = fmaxf(r0, 0.f);
            op[(size_t)o1 * IMG] = fmaxf(r1, 0.f);
        }
    }
}

// ---------------------------------------------------------------------------
// Copy x into channels 12..21 of bufA (makes the dense-skip concat free).
// ---------------------------------------------------------------------------
__global__ void copy_x_kernel(const float* __restrict__ x, float* __restrict__ bufA)
{
    size_t idx = (size_t)blockIdx.x * blockDim.x + threadIdx.x;
    const size_t total = (size_t)NB * 10 * IMG;
    if (idx < total) {
        int p = (int)(idx % IMG);
        int c = (int)((idx / IMG) % 10);
        int b = (int)(idx / ((size_t)IMG * 10));
        bufA[((size_t)b * 22 + 12 + c) * IMG + p] = x[idx];
    }
}

// ---------------------------------------------------------------------------
// Final per-sample 1x1 conv: [B,22,H,W] x [B,11,22] -> [B,11,H,W]
// ---------------------------------------------------------------------------
__global__ __launch_bounds__(256)
void conv1x1_kernel(const float* __restrict__ in, const float* __restrict__ w4,
                    float* __restrict__ out)
{
    __shared__ float s_w[11 * 22];
    const int b   = blockIdx.y;
    const int tid = threadIdx.x;
    if (tid < 242) s_w[tid] = w4[b * 242 + tid];
    __syncthreads();

    const int p0 = blockIdx.x * (256 * 4) + tid;
    const float* inb = in  + (size_t)b * 22 * IMG;
    float*       ob  = out + (size_t)b * 11 * IMG;

    float acc[4][11];
    #pragma unroll
    for (int q = 0; q < 4; q++)
        #pragma unroll
        for (int o = 0; o < 11; o++) acc[q][o] = 0.f;

    #pragma unroll 2
    for (int i = 0; i < 22; i++) {
        float v[4];
        #pragma unroll
        for (int q = 0; q < 4; q++) v[q] = inb[(size_t)i * IMG + p0 + q * 256];
        #pragma unroll
        for (int o = 0; o < 11; o++) {
            float w = s_w[o * 22 + i];
            #pragma unroll
            for (int q = 0; q < 4; q++) acc[q][o] = fmaf(v[q], w, acc[q][o]);
        }
    }
    #pragma unroll
    for (int o = 0; o < 11; o++)
        #pragma unroll
        for (int q = 0; q < 4; q++)
            ob[(size_t)o * IMG + p0 + q * 256] = acc[q][o];
}

// ---------------------------------------------------------------------------

static int smem_bytes(int cinp) {
    // input tile (CHUNK=6) + 8-padded weights + BN consts
    return (6 * 10 * 66 + cinp * 9 * 8 + 16) * 4;
}

extern "C" void kernel_launch(void* const* d_in, const int* in_sizes, int n_in,
                              void* d_out, int out_size)
{
    const float* x   = (const float*)d_in[0];
    const float* w1  = (const float*)d_in[1];
    const float* w2  = (const float*)d_in[2];
    const float* w3  = (const float*)d_in[3];
    const float* w4  = (const float*)d_in[4];
    const float* gam = (const float*)d_in[5];
    const float* bet = (const float*)d_in[6];
    const float* mea = (const float*)d_in[7];
    const float* var = (const float*)d_in[8];
    float* out = (float*)d_out;

    float *bufA, *bufB, *bufC;
    cudaGetSymbolAddress((void**)&bufA, g_bufA);
    cudaGetSymbolAddress((void**)&bufB, g_bufB);
    cudaGetSymbolAddress((void**)&bufC, g_bufC);

    cudaFuncSetAttribute(conv3x3_bn_relu6<10,12,2>, cudaFuncAttributeMaxDynamicSharedMemorySize, smem_bytes(12));
    cudaFuncSetAttribute(conv3x3_bn_relu6<12,12,2>, cudaFuncAttributeMaxDynamicSharedMemorySize, smem_bytes(12));
    cudaFuncSetAttribute(conv3x3_bn_relu6<22,24,4>, cudaFuncAttributeMaxDynamicSharedMemorySize, smem_bytes(24));
    cudaFuncSetAttribute(conv3x3_bn_relu6<24,24,4>, cudaFuncAttributeMaxDynamicSharedMemorySize, smem_bytes(24));
    cudaFuncSetAttribute(conv3x3_bn_relu6<24,24,2>, cudaFuncAttributeMaxDynamicSharedMemorySize, smem_bytes(24));

    const dim3 g12(2 * 2, 16, NB);   // COUT=12: 2 x-tiles * 2 oc-halves
    const dim3 g24(2 * 4, 16, NB);   // COUT=24: 2 x-tiles * 4 oc-quarters

    // x -> bufA channels 12..21 (skip-concat source, written once per launch)
    copy_x_kernel<<<(NB * 10 * IMG + 255) / 256, 256>>>(x, bufA);

    // ---- stage 1 ----  (BN offsets: 0,12,24)
    conv3x3_bn_relu6<10,12,2><<<g12, 128, smem_bytes(12)>>>(x,    10, w1, 3672,    0, gam,bet,mea,var,   0, bufB, 24);
    conv3x3_bn_relu6<12,12,2><<<g12, 128, smem_bytes(12)>>>(bufB, 24, w1, 3672, 1080, gam,bet,mea,var,  12, bufC, 24);
    conv3x3_bn_relu6<12,12,2><<<g12, 128, smem_bytes(12)>>>(bufC, 24, w1, 3672, 2376, gam,bet,mea,var,  24, bufA, 22);
    // ---- stage 2 ----  (BN offsets: 36,60,84)
    conv3x3_bn_relu6<22,24,4><<<g24, 128, smem_bytes(24)>>>(bufA, 22, w2, 12528,    0, gam,bet,mea,var,  36, bufB, 24);
    conv3x3_bn_relu6<24,24,4><<<g24, 128, smem_bytes(24)>>>(bufB, 24, w2, 12528, 4752, gam,bet,mea,var,  60, bufC, 24);
    conv3x3_bn_relu6<24,24,2><<<g12, 128, smem_bytes(24)>>>(bufC, 24, w2, 12528, 9936, gam,bet,mea,var,  84, bufA, 22);
    // ---- stage 3 ----  (BN offsets: 96,120,144)
    conv3x3_bn_relu6<22,24,4><<<g24, 128, smem_bytes(24)>>>(bufA, 22, w3, 12528,    0, gam,bet,mea,var,  96, bufB, 24);
    conv3x3_bn_relu6<24,24,4><<<g24, 128, smem_bytes(24)>>>(bufB, 24, w3, 12528, 4752, gam,bet,mea,var, 120, bufC, 24);
    conv3x3_bn_relu6<24,24,2><<<g12, 128, smem_bytes(24)>>>(bufC, 24, w3, 12528, 9936, gam,bet,mea,var, 144, bufA, 22);
    // ---- stage 4: 1x1 predictor ----
    conv1x1_kernel<<<dim3(IMG / (256 * 4), NB), 256>>>(bufA, w4, out);
}

// round 9
// speedup vs baseline: 1.1987x; 1.1987x over previous
#include <cuda_runtime.h>

#define HW   128
#define IMG  (HW*HW)
#define NB   64

typedef unsigned long long u64;

// Scratch buffers (allocation-free rule: __device__ globals)
__device__ float g_bufA[(size_t)NB * 22 * IMG];  // 22-ch concat buffer; x lives in ch 12..21
__device__ float g_bufB[(size_t)NB * 24 * IMG];
__device__ float g_bufC[(size_t)NB * 24 * IMG];

__device__ __forceinline__ u64 pack2(float v) {
    u64 r; unsigned int x = __float_as_uint(v);
    asm("mov.b64 %0, {%1, %1};" : "=l"(r) : "r"(x));
    return r;
}
__device__ __forceinline__ u64 fma2(u64 a, u64 b, u64 c) {
    u64 d;
    asm("fma.rn.f32x2 %0, %1, %2, %3;" : "=l"(d) : "l"(a), "l"(b), "l"(c));
    return d;
}
__device__ __forceinline__ float2 unpack2(u64 v) {
    unsigned int lo, hi;
    asm("mov.b64 {%0, %1}, %2;" : "=r"(lo), "=r"(hi) : "l"(v));
    return make_float2(__uint_as_float(lo), __uint_as_float(hi));
}

// ---------------------------------------------------------------------------
// Fused per-sample 3x3 conv + eval-BN + ReLU, 12 output channels per CTA.
// R4 structure (proven best): 128 threads, tile 64x8, T=4 rows/thread,
// staged input chunk + batched 3-vec weight preload -> 24-FFMA2 blocks.
// THIS ROUND: 6 CTAs/SM everywhere (regs capped 84; smem <= 37KB/CTA).
//   CIN=10: CHUNK=10, NCH=1 (no pad)
//   CIN=12: CHUNK=12, NCH=1
//   CIN=22/24: CINP=24 (zero-pad), CHUNK=8, NCH=3
// 24-out layers split into two output halves (NHALF=2).
// ---------------------------------------------------------------------------
template<int CIN, int CINP, int CHUNK, int NHALF>
__global__ __launch_bounds__(128, 6)
void conv3x3_bn_relu12(const float* __restrict__ in, int in_nch,
                       const float* __restrict__ wflat, int wP, int wbase,
                       const float* __restrict__ gam, const float* __restrict__ bet,
                       const float* __restrict__ mea, const float* __restrict__ varr,
                       int bnoff,
                       float* __restrict__ out, int out_nch)
{
    constexpr int COUT   = 12;
    constexpr int T      = 4;
    constexpr int TILE_X = 64;
    constexpr int TILE_Y = 8;
    constexpr int TXW    = TILE_X + 2;   // 66
    constexpr int TYH    = TILE_Y + 2;   // 10
    constexpr int NCH    = CINP / CHUNK;
    constexpr int NT     = 128;

    extern __shared__ float smem[];
    float* s_in = smem;                          // CHUNK * TYH * TXW floats
    float* s_w  = s_in + CHUNK * TYH * TXW;      // CINP * 9 * 12 (layout [i][k][o])
    float* s_sc = s_w + CINP * 9 * COUT;         // 12
    float* s_bi = s_sc + COUT;                   // 12

    const int tid  = threadIdx.x;
    const int b    = blockIdx.z;
    const int half   = blockIdx.x & (NHALF - 1);
    const int ochoff = half * 12;
    const int gx0  = (blockIdx.x / NHALF) * TILE_X;
    const int gy0  = blockIdx.y * TILE_Y;

    // --- load + repack weights: [o][i][k] (gmem) -> [i][k][o] (smem), pad i>=CIN -> 0 ---
    const float* wsrc = wflat + (size_t)b * wP + wbase + (size_t)ochoff * CIN * 9;
    for (int idx = tid; idx < CINP * 9 * COUT; idx += NT) {
        int o = idx % COUT;
        int r = idx / COUT;
        int k = r % 9;
        int i = r / 9;
        s_w[idx] = (i < CIN) ? wsrc[(o * CIN + i) * 9 + k] : 0.f;
    }
    if (tid < COUT) {
        int c = bnoff + ochoff + tid;
        float g = gam[c], bb = bet[c], m = mea[c], v = varr[c];
        float inv = g * rsqrtf(v + 1e-5f);
        s_sc[tid] = inv;
        s_bi[tid] = bb - m * inv;
    }

    const int lane = tid & 31;
    const int warp = tid >> 5;
    const int xl   = (warp & 1) * 32 + lane;   // 0..63
    const int y0   = (warp >> 1) * T;          // 0,4

    u64 acc[T][6];
    #pragma unroll
    for (int p = 0; p < T; p++)
        #pragma unroll
        for (int u = 0; u < 6; u++) acc[p][u] = 0ull;

    const ulonglong2* w16 = (const ulonglong2*)s_w;   // 3 vec per (i,k)
    const float* inb = in + (size_t)b * in_nch * IMG;

    for (int ch = 0; ch < NCH; ch++) {
        __syncthreads();
        // --- stage CHUNK input channels (halo, zero-padded) into smem ---
        #pragma unroll 1
        for (int idx = tid; idx < CHUNK * TYH * TXW; idx += NT) {
            int c = idx % TXW;
            int r = (idx / TXW) % TYH;
            int i = idx / (TXW * TYH);
            int ii = ch * CHUNK + i;
            int gy = gy0 - 1 + r, gx = gx0 - 1 + c;
            float v = 0.f;
            if ((CINP == CIN || ii < CIN) && (unsigned)gy < HW && (unsigned)gx < HW)
                v = inb[(size_t)ii * IMG + gy * HW + gx];
            s_in[idx] = v;
        }
        __syncthreads();

        #pragma unroll 2
        for (int i = 0; i < CHUNK; i++) {
            const int ii = ch * CHUNK + i;
            const float* srow = &s_in[(i * TYH + y0) * TXW + xl];
            #pragma unroll
            for (int kx = 0; kx < 3; kx++) {
                // load the T+2 rows this thread needs, once per kx
                u64 vr[T + 2];
                #pragma unroll
                for (int r = 0; r < T + 2; r++)
                    vr[r] = pack2(srow[r * TXW + kx]);
                #pragma unroll
                for (int ky = 0; ky < 3; ky++) {
                    // 12 out-channel weights for (ii, ky, kx): 3x LDS.128 broadcast
                    const ulonglong2* wp = &w16[(size_t)(ii * 9 + ky * 3 + kx) * 3];
                    u64 wv[6];
                    ulonglong2 w0 = wp[0], w1 = wp[1], w2 = wp[2];
                    wv[0] = w0.x; wv[1] = w0.y;
                    wv[2] = w1.x; wv[3] = w1.y;
                    wv[4] = w2.x; wv[5] = w2.y;
                    #pragma unroll
                    for (int p = 0; p < T; p++)
                        #pragma unroll
                        for (int u = 0; u < 6; u++)
                            acc[p][u] = fma2(vr[p + ky], wv[u], acc[p][u]);
                }
            }
        }
    }

    // --- epilogue: BN (eval) + ReLU + store ---
    float* ob = out + (size_t)b * out_nch * IMG + (size_t)ochoff * IMG;
    #pragma unroll
    for (int p = 0; p < T; p++) {
        const int y = gy0 + y0 + p;
        const int x = gx0 + xl;
        float* op = ob + y * HW + x;
        #pragma unroll
        for (int u = 0; u < 6; u++) {
            float2 a = unpack2(acc[p][u]);
            int o0 = 2 * u, o1 = 2 * u + 1;
            float r0 = fmaf(a.x, s_sc[o0], s_bi[o0]);
            float r1 = fmaf(a.y, s_sc[o1], s_bi[o1]);
            op[(size_t)o0 * IMG] = fmaxf(r0, 0.f);
            op[(size_t)o1 * IMG] = fmaxf(r1, 0.f);
        }
    }
}

// ---------------------------------------------------------------------------
// Copy x into channels 12..21 of bufA (makes the dense-skip concat free).
// ---------------------------------------------------------------------------
__global__ void copy_x_kernel(const float* __restrict__ x, float* __restrict__ bufA)
{
    size_t idx = (size_t)blockIdx.x * blockDim.x + threadIdx.x;
    const size_t total = (size_t)NB * 10 * IMG;
    if (idx < total) {
        int p = (int)(idx % IMG);
        int c = (int)((idx / IMG) % 10);
        int b = (int)(idx / ((size_t)IMG * 10));
        bufA[((size_t)b * 22 + 12 + c) * IMG + p] = x[idx];
    }
}

// ---------------------------------------------------------------------------
// Final per-sample 1x1 conv: [B,22,H,W] x [B,11,22] -> [B,11,H,W]
// ---------------------------------------------------------------------------
__global__ __launch_bounds__(256)
void conv1x1_kernel(const float* __restrict__ in, const float* __restrict__ w4,
                    float* __restrict__ out)
{
    __shared__ float s_w[11 * 22];
    const int b   = blockIdx.y;
    const int tid = threadIdx.x;
    if (tid < 242) s_w[tid] = w4[b * 242 + tid];
    __syncthreads();

    const int p0 = blockIdx.x * (256 * 4) + tid;
    const float* inb = in  + (size_t)b * 22 * IMG;
    float*       ob  = out + (size_t)b * 11 * IMG;

    float acc[4][11];
    #pragma unroll
    for (int q = 0; q < 4; q++)
        #pragma unroll
        for (int o = 0; o < 11; o++) acc[q][o] = 0.f;

    #pragma unroll 2
    for (int i = 0; i < 22; i++) {
        float v[4];
        #pragma unroll
        for (int q = 0; q < 4; q++) v[q] = inb[(size_t)i * IMG + p0 + q * 256];
        #pragma unroll
        for (int o = 0; o < 11; o++) {
            float w = s_w[o * 22 + i];
            #pragma unroll
            for (int q = 0; q < 4; q++) acc[q][o] = fmaf(v[q], w, acc[q][o]);
        }
    }
    #pragma unroll
    for (int o = 0; o < 11; o++)
        #pragma unroll
        for (int q = 0; q < 4; q++)
            ob[(size_t)o * IMG + p0 + q * 256] = acc[q][o];
}

// ---------------------------------------------------------------------------

static int smem_bytes(int cinp, int chunk) {
    return (chunk * 10 * 66 + cinp * 9 * 12 + 24) * 4;
}

extern "C" void kernel_launch(void* const* d_in, const int* in_sizes, int n_in,
                              void* d_out, int out_size)
{
    const float* x   = (const float*)d_in[0];
    const float* w1  = (const float*)d_in[1];
    const float* w2  = (const float*)d_in[2];
    const float* w3  = (const float*)d_in[3];
    const float* w4  = (const float*)d_in[4];
    const float* gam = (const float*)d_in[5];
    const float* bet = (const float*)d_in[6];
    const float* mea = (const float*)d_in[7];
    const float* var = (const float*)d_in[8];
    float* out = (float*)d_out;

    float *bufA, *bufB, *bufC;
    cudaGetSymbolAddress((void**)&bufA, g_bufA);
    cudaGetSymbolAddress((void**)&bufB, g_bufB);
    cudaGetSymbolAddress((void**)&bufC, g_bufC);

    // opt-in to >48KB dynamic smem (idempotent; host-side, capture-safe)
    cudaFuncSetAttribute((const void*)conv3x3_bn_relu12<10,10,10,1>, cudaFuncAttributeMaxDynamicSharedMemorySize, smem_bytes(10,10));
    cudaFuncSetAttribute((const void*)conv3x3_bn_relu12<12,12,12,1>, cudaFuncAttributeMaxDynamicSharedMemorySize, smem_bytes(12,12));
    cudaFuncSetAttribute((const void*)conv3x3_bn_relu12<22,24,8,2>,  cudaFuncAttributeMaxDynamicSharedMemorySize, smem_bytes(24,8));
    cudaFuncSetAttribute((const void*)conv3x3_bn_relu12<24,24,8,2>,  cudaFuncAttributeMaxDynamicSharedMemorySize, smem_bytes(24,8));
    cudaFuncSetAttribute((const void*)conv3x3_bn_relu12<24,24,8,1>,  cudaFuncAttributeMaxDynamicSharedMemorySize, smem_bytes(24,8));

    const dim3 g1(2, 16, NB);   // NHALF=1: 2 x-tiles, 16 y-tiles
    const dim3 g2(4, 16, NB);   // NHALF=2: 2 x-tiles * 2 output halves

    // x -> bufA channels 12..21 (skip-concat source, written once per launch)
    copy_x_kernel<<<(NB * 10 * IMG + 255) / 256, 256>>>(x, bufA);

    // ---- stage 1 ----  (BN offsets: 0,12,24)
    conv3x3_bn_relu12<10,10,10,1><<<g1, 128, smem_bytes(10,10)>>>(x,    10, w1, 3672,    0, gam,bet,mea,var,   0, bufB, 24);
    conv3x3_bn_relu12<12,12,12,1><<<g1, 128, smem_bytes(12,12)>>>(bufB, 24, w1, 3672, 1080, gam,bet,mea,var,  12, bufC, 24);
    conv3x3_bn_relu12<12,12,12,1><<<g1, 128, smem_bytes(12,12)>>>(bufC, 24, w1, 3672, 2376, gam,bet,mea,var,  24, bufA, 22);
    // ---- stage 2 ----  (BN offsets: 36,60,84)
    conv3x3_bn_relu12<22,24,8,2><<<g2, 128, smem_bytes(24,8)>>>(bufA, 22, w2, 12528,    0, gam,bet,mea,var,  36, bufB, 24);
    conv3x3_bn_relu12<24,24,8,2><<<g2, 128, smem_bytes(24,8)>>>(bufB, 24, w2, 12528, 4752, gam,bet,mea,var,  60, bufC, 24);
    conv3x3_bn_relu12<24,24,8,1><<<g1, 128, smem_bytes(24,8)>>>(bufC, 24, w2, 12528, 9936, gam,bet,mea,var,  84, bufA, 22);
    // ---- stage 3 ----  (BN offsets: 96,120,144)
    conv3x3_bn_relu12<22,24,8,2><<<g2, 128, smem_bytes(24,8)>>>(bufA, 22, w3, 12528,    0, gam,bet,mea,var,  96, bufB, 24);
    conv3x3_bn_relu12<24,24,8,2><<<g2, 128, smem_bytes(24,8)>>>(bufB, 24, w3, 12528, 4752, gam,bet,mea,var, 120, bufC, 24);
    conv3x3_bn_relu12<24,24,8,1><<<g1, 128, smem_bytes(24,8)>>>(bufC, 24, w3, 12528, 9936, gam,bet,mea,var, 144, bufA, 22);
    // ---- stage 4: 1x1 predictor ----
    conv1x1_kernel<<<dim3(IMG / (256 * 4), NB), 256>>>(bufA, w4, out);
}

// round 10
// speedup vs baseline: 1.9716x; 1.6448x over previous
#include <cuda_runtime.h>
#include <cuda_bf16.h>

#define HW    128
#define IMG   (HW*HW)
#define BATCH 64

// Scratch buffers (allocation-free rule: __device__ globals)
__device__ float g_bufA[(size_t)BATCH * 22 * IMG];  // 22-ch concat; x lives in ch 12..21
__device__ float g_bufB[(size_t)BATCH * 24 * IMG];
__device__ float g_bufC[(size_t)BATCH * 24 * IMG];

// ---------------------------------------------------------------------------
// bf16 split helpers: f = hi + lo with hi = bf16_rn(f), lo = bf16_rn(f - hi).
// Products hi*hi, hi*lo, lo*hi in bf16 MMA w/ fp32 accum give ~1e-5 rel err.
// ---------------------------------------------------------------------------
__device__ __forceinline__ void split2(float f0, float f1, unsigned& hi, unsigned& lo) {
    __nv_bfloat16 h0 = __float2bfloat16(f0);
    __nv_bfloat16 h1 = __float2bfloat16(f1);
    __nv_bfloat16 l0 = __float2bfloat16(f0 - __bfloat162float(h0));
    __nv_bfloat16 l1 = __float2bfloat16(f1 - __bfloat162float(h1));
    hi = ((unsigned)__bfloat16_as_ushort(h1) << 16) | (unsigned)__bfloat16_as_ushort(h0);
    lo = ((unsigned)__bfloat16_as_ushort(l1) << 16) | (unsigned)__bfloat16_as_ushort(l0);
}

// mma.sync m16n8k8 bf16: C[16x8,f32] += A[16x8,bf16] * B[8x8,bf16]
// A row-major frag: a0={A[g][2t],A[g][2t+1]}, a1={A[g+8][2t],A[g+8][2t+1]}
// B col frag:       b0={B[2t][g],B[2t+1][g]}   (k=2t,2t+1; n=g)
// C frag:           c0=C[g][2t] c1=C[g][2t+1] c2=C[g+8][2t] c3=C[g+8][2t+1]
__device__ __forceinline__ void mma_bf16(float c[4], unsigned a0, unsigned a1, unsigned b0) {
    asm("mma.sync.aligned.m16n8k8.row.col.f32.bf16.bf16.f32 "
        "{%0,%1,%2,%3}, {%4,%5}, {%6}, {%0,%1,%2,%3};"
        : "+f"(c[0]), "+f"(c[1]), "+f"(c[2]), "+f"(c[3])
        : "r"(a0), "r"(a1), "r"(b0));
}

// ---------------------------------------------------------------------------
// Per-sample 3x3 conv + eval-BN + ReLU via split-bf16 tensor-core MMA.
// CTA: 256 threads (8 warps), pixel tile 64x8 (halo 66x10).
// smem A: per-pixel record [hi bf16 x CINP | lo bf16 x CINP | pad], word
//   stride RSW (20 for CINP=16, 28 for CINP=24) -> conflict-free frag loads.
// smem B: weights pre-arranged in exact B-fragment order, hoisted to regs.
// Warp-tile: 2 M-blocks (16px each) x 1 n-block (8 oc), 3 split-term
//   accumulator sets each -> 6 independent HMMA chains.
// ---------------------------------------------------------------------------
template<int CIN, int CINP, int COUT, int COUTP>
__global__ __launch_bounds__(256, 2)
void conv3x3_mma(const float* __restrict__ in, int in_nch,
                 const float* __restrict__ wflat, int wP, int wbase,
                 const float* __restrict__ gam, const float* __restrict__ bet,
                 const float* __restrict__ mea, const float* __restrict__ varr,
                 int bnoff,
                 float* __restrict__ out, int out_nch)
{
    constexpr int KC   = CINP / 8;           // k-chunks of 8 channels
    constexpr int NBK  = COUTP / 8;          // n-blocks of 8 outputs
    constexpr int RSW  = (CINP == 16) ? 20 : 28;  // record stride (words)
    constexpr int CHW  = CINP / 2;           // lo-section word offset
    constexpr int TXW  = 66, TYH = 10;       // halo tile
    constexpr int NREC = TXW * TYH;          // 660 pixel records
    constexpr int BSL  = 9 * KC * 32;        // B slots per n-block

    extern __shared__ unsigned sm[];
    unsigned* s_a  = sm;                     // NREC * RSW
    unsigned* s_bh = s_a + NREC * RSW;       // NBK * BSL
    unsigned* s_bl = s_bh + NBK * BSL;       // NBK * BSL
    float*    s_sc = (float*)(s_bl + NBK * BSL);
    float*    s_bi = s_sc + COUTP;

    const int tid = threadIdx.x;
    const int bS  = blockIdx.z;
    const int gx0 = blockIdx.x * 64;
    const int gy0 = blockIdx.y * 8;

    // ---- stage A: float -> (hi,lo) bf16 pair records ----
    const float* inb = in + (size_t)bS * in_nch * IMG;
    for (int u = tid; u < (CINP / 2) * NREC; u += 256) {
        int x  = u % TXW;
        int r  = u / TXW;
        int y  = r % TYH;
        int cp = r / TYH;                    // channel pair
        int gy = gy0 - 1 + y, gx = gx0 - 1 + x;
        float f0 = 0.f, f1 = 0.f;
        bool inimg = ((unsigned)gy < HW) && ((unsigned)gx < HW);
        if (inimg && 2 * cp < CIN)     f0 = inb[(size_t)(2 * cp) * IMG + gy * HW + gx];
        if (inimg && 2 * cp + 1 < CIN) f1 = inb[(size_t)(2 * cp + 1) * IMG + gy * HW + gx];
        unsigned hi, lo; split2(f0, f1, hi, lo);
        int rec = y * TXW + x;
        s_a[rec * RSW + cp]       = hi;
        s_a[rec * RSW + CHW + cp] = lo;
    }

    // ---- prep B: gmem weights -> fragment-ordered smem (hi/lo) ----
    const float* wsrc = wflat + (size_t)bS * wP + wbase;
    for (int s = tid; s < NBK * BSL; s += 256) {
        int lane = s & 31;
        int r = s >> 5;
        int kc = r % KC;  r /= KC;
        int sh = r % 9;   r /= 9;
        int nb = r;
        int o  = nb * 8 + (lane >> 2);       // n = g
        int i0 = kc * 8 + (lane & 3) * 2;    // k = 2t, 2t+1
        float w0 = (o < COUT && i0     < CIN) ? wsrc[(o * CIN + i0    ) * 9 + sh] : 0.f;
        float w1 = (o < COUT && i0 + 1 < CIN) ? wsrc[(o * CIN + i0 + 1) * 9 + sh] : 0.f;
        unsigned hi, lo; split2(w0, w1, hi, lo);
        s_bh[s] = hi;
        s_bl[s] = lo;
    }
    if (tid < COUTP) {
        float sc = 0.f, bi = 0.f;
        if (tid < COUT) {
            int c = bnoff + tid;
            float inv = gam[c] * rsqrtf(varr[c] + 1e-5f);
            sc = inv; bi = bet[c] - mea[c] * inv;
        }
        s_sc[tid] = sc; s_bi[tid] = bi;
    }
    __syncthreads();

    const int lane = tid & 31, warp = tid >> 5;
    const int g = lane >> 2, t = lane & 3;

    unsigned bh[9 * KC], bl[9 * KC];
    int cur_nb = -1;
    float* ob = out + (size_t)bS * out_nch * IMG;

    // warp-tiles: idx in [0, 16*NBK): n-block = idx>>4, M-pair = idx&15
    for (int j = 0; j < 2 * NBK; j++) {
        const int idx = warp + 8 * j;
        const int nb  = idx >> 4;
        const int mp  = idx & 15;
        if (nb != cur_nb) {
            cur_nb = nb;
            const unsigned* ph = s_bh + nb * BSL + lane;
            const unsigned* pl = s_bl + nb * BSL + lane;
            #pragma unroll
            for (int q = 0; q < 9 * KC; q++) { bh[q] = ph[q * 32]; bl[q] = pl[q * 32]; }
        }

        float acc[2][3][4];
        #pragma unroll
        for (int m = 0; m < 2; m++)
            #pragma unroll
            for (int e = 0; e < 3; e++)
                #pragma unroll
                for (int i = 0; i < 4; i++) acc[m][e][i] = 0.f;

        const int mb0 = mp * 2, mb1 = mp * 2 + 1;
        const int base0 = ((mb0 >> 2) * TXW + (mb0 & 3) * 16 + g) * RSW + t;
        const int base1 = ((mb1 >> 2) * TXW + (mb1 & 3) * 16 + g) * RSW + t;

        #pragma unroll
        for (int ky = 0; ky < 3; ky++)
            #pragma unroll
            for (int kx = 0; kx < 3; kx++)
                #pragma unroll
                for (int kc = 0; kc < KC; kc++) {
                    const int q   = (ky * 3 + kx) * KC + kc;
                    const int off = (ky * TXW + kx) * RSW + kc * 4;
                    const unsigned b_h = bh[q], b_l = bl[q];
                    {
                        unsigned ah0 = s_a[base0 + off];
                        unsigned ah1 = s_a[base0 + off + 8 * RSW];
                        unsigned al0 = s_a[base0 + off + CHW];
                        unsigned al1 = s_a[base0 + off + CHW + 8 * RSW];
                        mma_bf16(acc[0][0], ah0, ah1, b_h);
                        mma_bf16(acc[0][1], ah0, ah1, b_l);
                        mma_bf16(acc[0][2], al0, al1, b_h);
                    }
                    {
                        unsigned ah0 = s_a[base1 + off];
                        unsigned ah1 = s_a[base1 + off + 8 * RSW];
                        unsigned al0 = s_a[base1 + off + CHW];
                        unsigned al1 = s_a[base1 + off + CHW + 8 * RSW];
                        mma_bf16(acc[1][0], ah0, ah1, b_h);
                        mma_bf16(acc[1][1], ah0, ah1, b_l);
                        mma_bf16(acc[1][2], al0, al1, b_h);
                    }
                }

        // ---- epilogue: combine split terms, BN + ReLU, store ----
        const int o0 = nb * 8 + 2 * t, o1 = o0 + 1;
        const float sc0 = s_sc[o0], bi0 = s_bi[o0];
        const float sc1 = s_sc[o1], bi1 = s_bi[o1];
        #pragma unroll
        for (int m = 0; m < 2; m++) {
            const int mb = mp * 2 + m;
            const int y  = gy0 + (mb >> 2);
            const int x  = gx0 + (mb & 3) * 16 + g;
            float c0 = acc[m][0][0] + acc[m][1][0] + acc[m][2][0];
            float c1 = acc[m][0][1] + acc[m][1][1] + acc[m][2][1];
            float c2 = acc[m][0][2] + acc[m][1][2] + acc[m][2][2];
            float c3 = acc[m][0][3] + acc[m][1][3] + acc[m][2][3];
            float* p = ob + (size_t)y * HW + x;
            if (o0 < COUT) {
                p[(size_t)o0 * IMG]     = fmaxf(fmaf(c0, sc0, bi0), 0.f);
                p[(size_t)o0 * IMG + 8] = fmaxf(fmaf(c2, sc0, bi0), 0.f);
            }
            if (o1 < COUT) {
                p[(size_t)o1 * IMG]     = fmaxf(fmaf(c1, sc1, bi1), 0.f);
                p[(size_t)o1 * IMG + 8] = fmaxf(fmaf(c3, sc1, bi1), 0.f);
            }
        }
    }
}

// ---------------------------------------------------------------------------
// Copy x into channels 12..21 of bufA (makes the dense-skip concat free).
// ---------------------------------------------------------------------------
__global__ void copy_x_kernel(const float* __restrict__ x, float* __restrict__ bufA)
{
    size_t idx = (size_t)blockIdx.x * blockDim.x + threadIdx.x;
    const size_t total = (size_t)BATCH * 10 * IMG;
    if (idx < total) {
        int p = (int)(idx % IMG);
        int c = (int)((idx / IMG) % 10);
        int b = (int)(idx / ((size_t)IMG * 10));
        bufA[((size_t)b * 22 + 12 + c) * IMG + p] = x[idx];
    }
}

// ---------------------------------------------------------------------------
// Final per-sample 1x1 conv: [B,22,H,W] x [B,11,22] -> [B,11,H,W]
// ---------------------------------------------------------------------------
__global__ __launch_bounds__(256)
void conv1x1_kernel(const float* __restrict__ in, const float* __restrict__ w4,
                    float* __restrict__ out)
{
    __shared__ float s_w[11 * 22];
    const int b   = blockIdx.y;
    const int tid = threadIdx.x;
    if (tid < 242) s_w[tid] = w4[b * 242 + tid];
    __syncthreads();

    const int p0 = blockIdx.x * (256 * 4) + tid;
    const float* inb = in  + (size_t)b * 22 * IMG;
    float*       ob  = out + (size_t)b * 11 * IMG;

    float acc[4][11];
    #pragma unroll
    for (int q = 0; q < 4; q++)
        #pragma unroll
        for (int o = 0; o < 11; o++) acc[q][o] = 0.f;

    #pragma unroll 2
    for (int i = 0; i < 22; i++) {
        float v[4];
        #pragma unroll
        for (int q = 0; q < 4; q++) v[q] = inb[(size_t)i * IMG + p0 + q * 256];
        #pragma unroll
        for (int o = 0; o < 11; o++) {
            float w = s_w[o * 22 + i];
            #pragma unroll
            for (int q = 0; q < 4; q++) acc[q][o] = fmaf(v[q], w, acc[q][o]);
        }
    }
    #pragma unroll
    for (int o = 0; o < 11; o++)
        #pragma unroll
        for (int q = 0; q < 4; q++)
            ob[(size_t)o * IMG + p0 + q * 256] = acc[q][o];
}

// ---------------------------------------------------------------------------

static int smem_bytes_mma(int cinp, int coutp) {
    int kc  = cinp / 8, nbk = coutp / 8;
    int rsw = (cinp == 16) ? 20 : 28;
    return (660 * rsw + 2 * nbk * 9 * kc * 32 + 2 * coutp) * 4;
}

extern "C" void kernel_launch(void* const* d_in, const int* in_sizes, int n_in,
                              void* d_out, int out_size)
{
    const float* x   = (const float*)d_in[0];
    const float* w1  = (const float*)d_in[1];
    const float* w2  = (const float*)d_in[2];
    const float* w3  = (const float*)d_in[3];
    const float* w4  = (const float*)d_in[4];
    const float* gam = (const float*)d_in[5];
    const float* bet = (const float*)d_in[6];
    const float* mea = (const float*)d_in[7];
    const float* var = (const float*)d_in[8];
    float* out = (float*)d_out;

    float *bufA, *bufB, *bufC;
    cudaGetSymbolAddress((void**)&bufA, g_bufA);
    cudaGetSymbolAddress((void**)&bufB, g_bufB);
    cudaGetSymbolAddress((void**)&bufC, g_bufC);

    // opt-in to >48KB dynamic smem (idempotent; host-side, capture-safe)
    cudaFuncSetAttribute((const void*)conv3x3_mma<10,16,12,16>, cudaFuncAttributeMaxDynamicSharedMemorySize, smem_bytes_mma(16,16));
    cudaFuncSetAttribute((const void*)conv3x3_mma<12,16,12,16>, cudaFuncAttributeMaxDynamicSharedMemorySize, smem_bytes_mma(16,16));
    cudaFuncSetAttribute((const void*)conv3x3_mma<22,24,24,24>, cudaFuncAttributeMaxDynamicSharedMemorySize, smem_bytes_mma(24,24));
    cudaFuncSetAttribute((const void*)conv3x3_mma<24,24,24,24>, cudaFuncAttributeMaxDynamicSharedMemorySize, smem_bytes_mma(24,24));
    cudaFuncSetAttribute((const void*)conv3x3_mma<24,24,12,16>, cudaFuncAttributeMaxDynamicSharedMemorySize, smem_bytes_mma(24,16));

    const dim3 grd(2, 16, BATCH);   // 64x8 pixel tiles

    // x -> bufA channels 12..21 (skip-concat source, written once per launch)
    copy_x_kernel<<<(BATCH * 10 * IMG + 255) / 256, 256>>>(x, bufA);

    // ---- stage 1 ----  (BN offsets: 0,12,24)
    conv3x3_mma<10,16,12,16><<<grd, 256, smem_bytes_mma(16,16)>>>(x,    10, w1, 3672,    0, gam,bet,mea,var,   0, bufB, 24);
    conv3x3_mma<12,16,12,16><<<grd, 256, smem_bytes_mma(16,16)>>>(bufB, 24, w1, 3672, 1080, gam,bet,mea,var,  12, bufC, 24);
    conv3x3_mma<12,16,12,16><<<grd, 256, smem_bytes_mma(16,16)>>>(bufC, 24, w1, 3672, 2376, gam,bet,mea,var,  24, bufA, 22);
    // ---- stage 2 ----  (BN offsets: 36,60,84)
    conv3x3_mma<22,24,24,24><<<grd, 256, smem_bytes_mma(24,24)>>>(bufA, 22, w2, 12528,    0, gam,bet,mea,var,  36, bufB, 24);
    conv3x3_mma<24,24,24,24><<<grd, 256, smem_bytes_mma(24,24)>>>(bufB, 24, w2, 12528, 4752, gam,bet,mea,var,  60, bufC, 24);
    conv3x3_mma<24,24,12,16><<<grd, 256, smem_bytes_mma(24,16)>>>(bufC, 24, w2, 12528, 9936, gam,bet,mea,var,  84, bufA, 22);
    // ---- stage 3 ----  (BN offsets: 96,120,144)
    conv3x3_mma<22,24,24,24><<<grd, 256, smem_bytes_mma(24,24)>>>(bufA, 22, w3, 12528,    0, gam,bet,mea,var,  96, bufB, 24);
    conv3x3_mma<24,24,24,24><<<grd, 256, smem_bytes_mma(24,24)>>>(bufB, 24, w3, 12528, 4752, gam,bet,mea,var, 120, bufC, 24);
    conv3x3_mma<24,24,12,16><<<grd, 256, smem_bytes_mma(24,16)>>>(bufC, 24, w3, 12528, 9936, gam,bet,mea,var, 144, bufA, 22);
    // ---- stage 4: 1x1 predictor ----
    conv1x1_kernel<<<dim3(IMG / (256 * 4), BATCH), 256>>>(bufA, w4, out);
}